// round 17
// baseline (speedup 1.0000x reference)
#include <cuda_runtime.h>
#include <cuda_fp16.h>
#include <stdint.h>

// Problem constants
#define Bd   2
#define Nseq 2048
#define Dm   1024
#define Hh   16
#define HD   64
#define SCALE 0.125f
#define Kdim 1024

// ---------------- device scratch (no allocations allowed) -------------------
__device__ __half g_x[Bd*Nseq*Dm];          // x fp16
__device__ __half g_wq[3*Dm*Kdim];          // w_qkv^T fp16 [3072,1024]
__device__ __half g_wp[Dm*Kdim];            // w_proj^T fp16 [1024,1024]
__device__ __half g_q[Bd*Hh*Nseq*HD];       // q*scale fp16 [B,H,N,64]
__device__ __half g_k[Bd*Hh*Nseq*HD];
__device__ __half g_v[Bd*Hh*Nseq*HD];
__device__ __half g_a[Bd*Nseq*Dm];          // attention out fp16

// ---------------- helpers ----------------------------------------------------
__device__ __forceinline__ uint32_t smem_u32(const void* p) {
    return (uint32_t)__cvta_generic_to_shared(p);
}
__device__ __forceinline__ void mma_f16(float (&d)[4], const uint32_t (&a)[4],
                                        const uint32_t (&b)[2]) {
    asm volatile(
        "mma.sync.aligned.m16n8k16.row.col.f32.f16.f16.f32 "
        "{%0,%1,%2,%3}, {%4,%5,%6,%7}, {%8,%9}, {%0,%1,%2,%3};"
        : "+f"(d[0]), "+f"(d[1]), "+f"(d[2]), "+f"(d[3])
        : "r"(a[0]), "r"(a[1]), "r"(a[2]), "r"(a[3]), "r"(b[0]), "r"(b[1]));
}
__device__ __forceinline__ void ldsm4(uint32_t (&r)[4], uint32_t addr) {
    asm volatile("ldmatrix.sync.aligned.m8n8.x4.shared.b16 {%0,%1,%2,%3}, [%4];"
        : "=r"(r[0]), "=r"(r[1]), "=r"(r[2]), "=r"(r[3]) : "r"(addr));
}
__device__ __forceinline__ void ldsm4t(uint32_t (&r)[4], uint32_t addr) {
    asm volatile("ldmatrix.sync.aligned.m8n8.x4.trans.shared.b16 {%0,%1,%2,%3}, [%4];"
        : "=r"(r[0]), "=r"(r[1]), "=r"(r[2]), "=r"(r[3]) : "r"(addr));
}
__device__ __forceinline__ uint32_t pack_f16(float lo, float hi) {
    __half2 h = __floats2half2_rn(lo, hi);
    return *(uint32_t*)&h;
}
__device__ __forceinline__ void cp16(uint32_t s, const void* g) {
    asm volatile("cp.async.cg.shared.global [%0], [%1], 16;" :: "r"(s), "l"(g));
}
#define CP_COMMIT() asm volatile("cp.async.commit_group;" ::: "memory")
#define CP_WAIT1()  asm volatile("cp.async.wait_group 1;" ::: "memory")
#define CP_WAIT0()  asm volatile("cp.async.wait_group 0;" ::: "memory")

// ---------------- fused convert pre-pass -------------------------------------
#define CONV_XB   4096
#define CONV_QB   3072
#define CONV_PB   1024
#define CONV_BLKS (CONV_XB + CONV_QB + CONV_PB)

__global__ void __launch_bounds__(256) conv_all_kernel(
    const float* __restrict__ x, const float* __restrict__ wq,
    const float* __restrict__ wp)
{
    int bid = blockIdx.x;
    if (bid < CONV_XB) {
        int i4 = (bid * 256 + threadIdx.x) * 4;
        float4 v = *(const float4*)&x[i4];
        *(__half2*)&g_x[i4]     = __floats2half2_rn(v.x, v.y);
        *(__half2*)&g_x[i4 + 2] = __floats2half2_rn(v.z, v.w);
        return;
    }
    __shared__ float t[32][33];
    const float* w;
    __half* dst;
    int N, n0, k0;
    if (bid < CONV_XB + CONV_QB) {
        int lb = bid - CONV_XB;              // 96 x 32
        w = wq; dst = g_wq; N = 3 * Dm;
        n0 = (lb % 96) * 32; k0 = (lb / 96) * 32;
    } else {
        int lb = bid - CONV_XB - CONV_QB;    // 32 x 32
        w = wp; dst = g_wp; N = Dm;
        n0 = (lb % 32) * 32; k0 = (lb / 32) * 32;
    }
    int tx = threadIdx.x & 31, ty = threadIdx.x >> 5;   // 32 x 8
    #pragma unroll
    for (int i = 0; i < 4; i++) {
        int k = k0 + ty + i * 8;
        t[ty + i * 8][tx] = w[(size_t)k * N + n0 + tx];
    }
    __syncthreads();
    #pragma unroll
    for (int i = 0; i < 4; i++) {
        int n = n0 + ty + i * 8;
        dst[(size_t)n * Kdim + k0 + tx] = __float2half_rn(t[tx][ty + i * 8]);
    }
}

// ---------------- HMMA GEMM: persistent grid, K-tile 64, 2-stage -------------
// 16 warps (4m x 4n), warp tile 32x32, 128x128 block tile. 2 CTA/SM.
#define GSTAGE 36864
#define GEMM_DSMEM (2 * GSTAGE)
#define GEMM_NT (Kdim / 64)
#define PERSIST_BLKS 296

template<int MODE>
__global__ void __launch_bounds__(512, 2) mma_gemm(const float* __restrict__ bias,
                                                   float* __restrict__ C, int Nc) {
    extern __shared__ char dyn[];
    const uint32_t sbase = smem_u32(dyn);

    const int tid = threadIdx.x, lane = tid & 31, wid = tid >> 5;
    const __half* A = MODE ? g_x : g_a;
    const __half* B = MODE ? g_wq : g_wp;
    const int wm = (wid >> 2) * 32, wn = (wid & 3) * 32;
    const int ntx = Nc / 128;
    const int ntiles = ((Bd * Nseq) / 128) * ntx;

    const uint32_t lmr = (uint32_t)(lane & 15);
    const uint32_t lmc = (uint32_t)((lane >> 4) * 16);

    for (int tile = blockIdx.x; tile < ntiles; tile += gridDim.x) {
        const int m0 = (tile / ntx) * 128;
        const int n0 = (tile % ntx) * 128;

        float acc[2][4][4] = {};

        auto fill = [&](int st, int k0) {
            uint32_t sb = sbase + st * GSTAGE;
            #pragma unroll
            for (int l = 0; l < 4; l++) {
                int s = tid + l * 512;
                int r = s >> 3, c = s & 7;
                if (r < 128) {
                    cp16(sb + (uint32_t)(r * 144 + c * 16),
                         &A[(size_t)(m0 + r) * Kdim + k0 + c * 8]);
                } else {
                    cp16(sb + 18432 + (uint32_t)((r - 128) * 144 + c * 16),
                         &B[(size_t)(n0 + r - 128) * Kdim + k0 + c * 8]);
                }
            }
        };

        __syncthreads();   // previous tile's compute done before refilling stage 0
        fill(0, 0);
        CP_COMMIT();

        for (int t = 0; t < GEMM_NT; t++) {
            CP_WAIT0();
            __syncthreads();
            if (t + 1 < GEMM_NT) { fill((t + 1) & 1, (t + 1) * 64); CP_COMMIT(); }

            const uint32_t sb = sbase + (t & 1) * GSTAGE;
            const uint32_t aA = sb, aB = sb + 18432;

            #pragma unroll
            for (int kt = 0; kt < 4; kt++) {
                uint32_t a[2][4], b[4][2];
                #pragma unroll
                for (int mi = 0; mi < 2; mi++) {
                    uint32_t ro = (wm + mi * 16 + lmr) * 144 + kt * 32 + lmc;
                    ldsm4(a[mi], aA + ro);
                }
                #pragma unroll
                for (int g = 0; g < 2; g++) {
                    uint32_t ro = (wn + g * 16 + lmr) * 144 + kt * 32 + lmc;
                    uint32_t tt[4];
                    ldsm4(tt, aB + ro);
                    b[2*g][0] = tt[0]; b[2*g][1] = tt[2];
                    b[2*g+1][0] = tt[1]; b[2*g+1][1] = tt[3];
                }
                #pragma unroll
                for (int mi = 0; mi < 2; mi++)
                    #pragma unroll
                    for (int ni = 0; ni < 4; ni++)
                        mma_f16(acc[mi][ni], a[mi], b[ni]);
            }
        }

        // epilogue
        #pragma unroll
        for (int mi = 0; mi < 2; mi++) {
            int r0 = m0 + wm + mi * 16 + (lane >> 2);
            #pragma unroll
            for (int ni = 0; ni < 4; ni++) {
                int col = n0 + wn + ni * 8 + 2 * (lane & 3);
                float b0 = bias[col], b1 = bias[col + 1];
                #pragma unroll
                for (int rr = 0; rr < 2; rr++) {
                    int row = r0 + rr * 8;
                    float v0 = acc[mi][ni][rr * 2 + 0] + b0;
                    float v1 = acc[mi][ni][rr * 2 + 1] + b1;
                    if (MODE == 0) {
                        *(float2*)&C[(size_t)row * Nc + col] = make_float2(v0, v1);
                    } else {
                        int bb = row >> 11, nn = row & 2047;
                        int which = col >> 10, rem = col & 1023;
                        int hh = rem >> 6, dd = rem & 63;
                        if (which == 0) { v0 *= SCALE; v1 *= SCALE; }
                        size_t idx = (((size_t)(bb * Hh + hh)) * Nseq + nn) * HD + dd;
                        __half* dst = (which == 0) ? g_q : (which == 1) ? g_k : g_v;
                        *(__half2*)&dst[idx] = __floats2half2_rn(v0, v1);
                    }
                }
            }
        }
    }
}

// ---------------- flash attention: persistent grid, cp.async 3-stage ---------
// 8 warps, Q-tile 128 (Q in registers), K-tile 64. Rows 128B fp16, pitch 144B.
// 512 (b,h,qt) tiles looped over 296 persistent blocks.
#define FSTAGE 18432
#define FLASH_DSMEM (3 * FSTAGE + 3 * 256)
#define FLASH_NT (Nseq / 64)
#define FLASH_TILES (Bd * Hh * (Nseq / 128))

__global__ void __launch_bounds__(256, 2) flash_mma(const float* __restrict__ attn_bias) {
    extern __shared__ char dyn[];
    const uint32_t sbase = smem_u32(dyn);
    const uint32_t sbias = sbase + 3 * FSTAGE;

    const int tid = threadIdx.x, lane = tid & 31, wid = tid >> 5;
    const int fr = tid >> 3, fc = tid & 7;   // row base (0..31), 16B chunk (0..7)

    for (int tile = blockIdx.x; tile < FLASH_TILES; tile += gridDim.x) {
        const int b  = tile >> 8;            // tile / 256
        const int rm = tile & 255;
        const int h  = rm >> 4;              // / 16
        const int q0 = (rm & 15) * 128;

        const size_t hoff = (size_t)((b * Hh + h) * Nseq) * HD;
        const __half *Qp = g_q + hoff, *Kp = g_k + hoff, *Vp = g_v + hoff;
        const float* biasg = attn_bias + b * Nseq;

        auto fill = [&](int st, int k0) {
            uint32_t sb = sbase + st * FSTAGE;
            #pragma unroll
            for (int half = 0; half < 2; half++) {
                int r = fr + half * 32;
                uint32_t o = (uint32_t)(r * 144 + fc * 16);
                size_t g = (size_t)(k0 + r) * HD + fc * 8;
                cp16(sb + o,        &Kp[g]);
                cp16(sb + 9216 + o, &Vp[g]);
            }
            if (tid < 16) cp16(sbias + st * 256 + tid * 16, &biasg[k0 + tid * 4]);
        };

        // ---- Q A-fragments directly from gmem ----
        uint32_t qf[4][4];
        {
            int r = q0 + wid * 16 + (lane >> 2);
            int c = 2 * (lane & 3);
            #pragma unroll
            for (int kf = 0; kf < 4; kf++) {
                #pragma unroll
                for (int e = 0; e < 4; e++) {
                    size_t g = (size_t)(r + (e & 1) * 8) * HD + kf * 16 + (e >> 1) * 8 + c;
                    qf[kf][e] = *(const uint32_t*)&Qp[g];
                }
            }
        }

        __syncthreads();   // previous tile's smem reads done before refilling
        fill(0, 0);  CP_COMMIT();
        fill(1, 64); CP_COMMIT();

        float O[8][4] = {};
        float mrow0 = -1e30f, mrow1 = -1e30f, lrow0 = 0.f, lrow1 = 0.f;

        for (int t = 0; t < FLASH_NT; t++) {
            if (t + 2 < FLASH_NT) CP_WAIT1(); else CP_WAIT0();
            __syncthreads();
            if (t + 2 < FLASH_NT) { fill((t + 2) % 3, (t + 2) * 64); CP_COMMIT(); }

            const uint32_t sb = sbase + (t % 3) * FSTAGE;
            const uint32_t aK = sb, aV = sb + 9216;
            const float* sB = (const float*)(dyn + 3 * FSTAGE + (t % 3) * 256);

            // ---- S = Q K^T ----
            float S[8][4] = {};
            #pragma unroll
            for (int kf = 0; kf < 4; kf++) {
                #pragma unroll
                for (int g = 0; g < 4; g++) {
                    uint32_t ro = (uint32_t)((g * 16 + (lane & 15)) * 144 + kf * 32 + (lane >> 4) * 16);
                    uint32_t tt[4], b0[2], b1[2];
                    ldsm4(tt, aK + ro);
                    b0[0] = tt[0]; b0[1] = tt[2]; b1[0] = tt[1]; b1[1] = tt[3];
                    mma_f16(S[2*g],   qf[kf], b0);
                    mma_f16(S[2*g+1], qf[kf], b1);
                }
            }

            // ---- bias + online softmax ----
            float mx0 = mrow0, mx1 = mrow1;
            #pragma unroll
            for (int nt = 0; nt < 8; nt++) {
                float2 bb = *(const float2*)&sB[nt * 8 + 2 * (lane & 3)];
                S[nt][0] += bb.x; S[nt][1] += bb.y;
                S[nt][2] += bb.x; S[nt][3] += bb.y;
                mx0 = fmaxf(mx0, fmaxf(S[nt][0], S[nt][1]));
                mx1 = fmaxf(mx1, fmaxf(S[nt][2], S[nt][3]));
            }
            mx0 = fmaxf(mx0, __shfl_xor_sync(0xffffffffu, mx0, 1));
            mx0 = fmaxf(mx0, __shfl_xor_sync(0xffffffffu, mx0, 2));
            mx1 = fmaxf(mx1, __shfl_xor_sync(0xffffffffu, mx1, 1));
            mx1 = fmaxf(mx1, __shfl_xor_sync(0xffffffffu, mx1, 2));
            float alpha0 = __expf(mrow0 - mx0), alpha1 = __expf(mrow1 - mx1);
            mrow0 = mx0; mrow1 = mx1;
            float sum0 = 0.f, sum1 = 0.f;
            #pragma unroll
            for (int nt = 0; nt < 8; nt++) {
                S[nt][0] = __expf(S[nt][0] - mx0); S[nt][1] = __expf(S[nt][1] - mx0);
                S[nt][2] = __expf(S[nt][2] - mx1); S[nt][3] = __expf(S[nt][3] - mx1);
                sum0 += S[nt][0] + S[nt][1];
                sum1 += S[nt][2] + S[nt][3];
            }
            sum0 += __shfl_xor_sync(0xffffffffu, sum0, 1);
            sum0 += __shfl_xor_sync(0xffffffffu, sum0, 2);
            sum1 += __shfl_xor_sync(0xffffffffu, sum1, 1);
            sum1 += __shfl_xor_sync(0xffffffffu, sum1, 2);
            lrow0 = lrow0 * alpha0 + sum0;
            lrow1 = lrow1 * alpha1 + sum1;
            #pragma unroll
            for (int dt = 0; dt < 8; dt++) {
                O[dt][0] *= alpha0; O[dt][1] *= alpha0;
                O[dt][2] *= alpha1; O[dt][3] *= alpha1;
            }

            // ---- P -> fp16 A-fragments ----
            uint32_t pf[4][4];
            #pragma unroll
            for (int kt = 0; kt < 4; kt++) {
                #pragma unroll
                for (int half = 0; half < 2; half++) {
                    int nt = 2 * kt + half;
                    pf[kt][half * 2 + 0] = pack_f16(S[nt][0], S[nt][1]);
                    pf[kt][half * 2 + 1] = pack_f16(S[nt][2], S[nt][3]);
                }
            }

            // ---- O += P V ----
            #pragma unroll
            for (int kt = 0; kt < 4; kt++) {
                #pragma unroll
                for (int g = 0; g < 4; g++) {
                    uint32_t ro = (uint32_t)((kt * 16 + (lane & 7) + 8 * ((lane >> 3) & 1)) * 144
                                             + g * 32 + (lane >> 4) * 16);
                    uint32_t tt[4], v0[2], v1[2];
                    ldsm4t(tt, aV + ro);
                    v0[0] = tt[0]; v0[1] = tt[1]; v1[0] = tt[2]; v1[1] = tt[3];
                    mma_f16(O[2*g],   pf[kt], v0);
                    mma_f16(O[2*g+1], pf[kt], v1);
                }
            }
        }

        // ---- epilogue: normalize, write fp16 attention output ----
        float inv0 = 1.f / lrow0, inv1 = 1.f / lrow1;
        int r0 = q0 + wid * 16 + (lane >> 2);
        #pragma unroll
        for (int dt = 0; dt < 8; dt++) {
            int col = h * HD + dt * 8 + 2 * (lane & 3);
            size_t i0 = (size_t)(b * Nseq + r0) * Dm + col;
            size_t i1 = (size_t)(b * Nseq + r0 + 8) * Dm + col;
            *(__half2*)&g_a[i0] = __floats2half2_rn(O[dt][0] * inv0, O[dt][1] * inv0);
            *(__half2*)&g_a[i1] = __floats2half2_rn(O[dt][2] * inv1, O[dt][3] * inv1);
        }
    }
}

// ---------------- launch -----------------------------------------------------
extern "C" void kernel_launch(void* const* d_in, const int* in_sizes, int n_in,
                              void* d_out, int out_size)
{
    const float* x         = (const float*)d_in[0];
    const float* attn_bias = (const float*)d_in[1];
    const float* w_qkv     = (const float*)d_in[2];
    const float* b_qkv     = (const float*)d_in[3];
    const float* w_proj    = (const float*)d_in[4];
    const float* b_proj    = (const float*)d_in[5];
    float* out = (float*)d_out;

    cudaFuncSetAttribute(mma_gemm<1>, cudaFuncAttributeMaxDynamicSharedMemorySize, GEMM_DSMEM);
    cudaFuncSetAttribute(mma_gemm<0>, cudaFuncAttributeMaxDynamicSharedMemorySize, GEMM_DSMEM);
    cudaFuncSetAttribute(flash_mma,   cudaFuncAttributeMaxDynamicSharedMemorySize, FLASH_DSMEM);

    // fused converts (x split + both weight transposes) in one launch
    conv_all_kernel<<<CONV_BLKS, 256>>>(x, w_qkv, w_proj);

    // QKV GEMM: persistent grid (768 tiles on 296 blocks)
    mma_gemm<1><<<PERSIST_BLKS, 512, GEMM_DSMEM>>>(b_qkv, nullptr, 3 * Dm);

    // flash attention: persistent grid (512 tiles on 296 blocks)
    flash_mma<<<PERSIST_BLKS, 256, FLASH_DSMEM>>>(attn_bias);

    // proj GEMM: 256 tiles on 256 blocks (persistent path, single pass)
    mma_gemm<0><<<256, 512, GEMM_DSMEM>>>(b_proj, out, Dm);
}